// round 7
// baseline (speedup 1.0000x reference)
#include <cuda_runtime.h>
#include <cuda_fp16.h>
#include <cstdint>

// Problem constants (fixed: x,y in f32[4,4096,128])
#define BATCH 4
#define NPTS  4096
#define DIM   128
#define INF_BITS 0x7f800000u

#define ROWB   256            // bytes per row in gmem (128 fp16)
#define SSTB   272            // smem row stride bytes (68 words, 68%32==4: ldmatrix conflict-free)

// ---------------- global scratch (allocation-free rule) ----------------
__device__ __half  g_Ax[BATCH * NPTS * DIM];
__device__ __half  g_By[BATCH * NPTS * DIM];
__device__ float    g_x2[BATCH * NPTS];
__device__ float    g_y2[BATCH * NPTS];
__device__ unsigned g_rowmin[BATCH * NPTS];  // RED.MIN accumulated (clamped >=0)
__device__ unsigned g_colmin[BATCH * NPTS];  // RED.MIN accumulated (clamped >=0)

// ---------------- smem layout (bytes): M=64 tile -> 2 CTAs/SM ----------------
#define A_OFF     0            // 64 * 272 = 17408
#define B0_OFF    17408        // 128 * 272 = 34816
#define B1_OFF    52224
#define SMEM_BYTES 87040

// ---------------- PTX helpers (sm_80+ / plain sm_100-safe) ----------------
__device__ __forceinline__ uint32_t smem_u32(const void* p) {
    uint32_t a;
    asm("{ .reg .u64 t; cvta.to.shared.u64 t, %1; cvt.u32.u64 %0, t; }" : "=r"(a) : "l"(p));
    return a;
}
__device__ __forceinline__ void cp_async16(uint32_t saddr, const void* g) {
    asm volatile("cp.async.cg.shared.global [%0], [%1], 16;" :: "r"(saddr), "l"(g));
}
#define CP_COMMIT() asm volatile("cp.async.commit_group;" ::: "memory")
#define CP_WAIT0()  asm volatile("cp.async.wait_group 0;" ::: "memory")

__device__ __forceinline__ void ldsm_x4(uint32_t* r, uint32_t addr) {
    asm volatile("ldmatrix.sync.aligned.m8n8.x4.shared.b16 {%0,%1,%2,%3}, [%4];"
                 : "=r"(r[0]), "=r"(r[1]), "=r"(r[2]), "=r"(r[3]) : "r"(addr));
}
__device__ __forceinline__ void ldsm_x2(uint32_t* r, uint32_t addr) {
    asm volatile("ldmatrix.sync.aligned.m8n8.x2.shared.b16 {%0,%1}, [%2];"
                 : "=r"(r[0]), "=r"(r[1]) : "r"(addr));
}
__device__ __forceinline__ void mma_f16(float* c, const uint32_t* a, const uint32_t* b) {
    asm volatile("mma.sync.aligned.m16n8k16.row.col.f32.f16.f16.f32 "
                 "{%0,%1,%2,%3}, {%4,%5,%6,%7}, {%8,%9}, {%0,%1,%2,%3};"
                 : "+f"(c[0]), "+f"(c[1]), "+f"(c[2]), "+f"(c[3])
                 : "r"(a[0]), "r"(a[1]), "r"(a[2]), "r"(a[3]), "r"(b[0]), "r"(b[1]));
}

// ---------------------------------------------------------------------------
// Kernel 1: fp16 convert + fp32 squared norms + min-array init. Warp per row.
// ---------------------------------------------------------------------------
__global__ void hd_prep(const float* __restrict__ x, const float* __restrict__ y) {
    int gtid = blockIdx.x * blockDim.x + threadIdx.x;
    if (gtid < BATCH * NPTS) {
        g_colmin[gtid] = INF_BITS;
        g_rowmin[gtid] = INF_BITS;
    }

    int warp = gtid >> 5;
    int lane = gtid & 31;
    bool isx = warp < BATCH * NPTS;
    int row = isx ? warp : warp - BATCH * NPTS;
    const float* src = (isx ? x : y) + (size_t)row * DIM;

    float4 v = ((const float4*)src)[lane];

    __half2 p0 = __floats2half2_rn(v.x, v.y);
    __half2 p1 = __floats2half2_rn(v.z, v.w);
    uint2 pw;
    pw.x = *(unsigned*)&p0;
    pw.y = *(unsigned*)&p1;

    __half* dst = (isx ? g_Ax : g_By) + (size_t)row * DIM;
    ((uint2*)dst)[lane] = pw;

    float s = v.x * v.x + v.y * v.y + v.z * v.z + v.w * v.w;
    #pragma unroll
    for (int o = 16; o > 0; o >>= 1) s += __shfl_xor_sync(0xffffffffu, s, o);
    if (lane == 0) {
        if (isx) g_x2[row] = s;
        else     g_y2[row] = s;
    }
}

// ---------------------------------------------------------------------------
// Kernel 2: fp16 mma.sync GEMM with fused min epilogue. M-tile = 64 rows of x,
// 256 CTAs (4 b x 64 n-tiles), 2 CTAs/SM: one CTA's epilogue hides under the
// other's HMMAs. Each CTA streams all 32 m-tiles of y (double-buffered).
// Warp layout: 8 warps = 2 (M) x 4 (N); warp tile 32x32.
// Mins deferred: rowmin accumulates (y2-2dot), colmin (x2-2dot); norms added
// and clamp applied at flush (min/max commute with the final clamp).
// ---------------------------------------------------------------------------
extern __shared__ unsigned char smem_raw[];

__global__ __launch_bounds__(256, 2)
void hd_main() {
    unsigned char* sm = smem_raw;
    const uint32_t sbase = smem_u32(sm);
    const int tid = threadIdx.x;
    const int wid = tid >> 5;
    const int ln  = tid & 31;
    const int wm  = wid >> 2;        // 0..1  (M half: 32 rows)
    const int wn  = wid & 3;         // 0..3  (N quarter: 32 cols)
    const int b   = blockIdx.x >> 6;
    const int n0  = (blockIdx.x & 63) * 64;

    // ---- prologue: async-load A tile (17 KB) and B tile 0 (34 KB) ----
    {
        const unsigned char* asrc = (const unsigned char*)(g_Ax + (size_t)(b * NPTS + n0) * DIM);
        const unsigned char* bsrc = (const unsigned char*)(g_By + (size_t)(b * NPTS) * DIM);
        #pragma unroll
        for (int it = 0; it < 4; it++) {       // A: 1024 chunks of 16B
            int idx = it * 256 + tid;
            int row = idx >> 4, c = idx & 15;
            cp_async16(sbase + A_OFF + row * SSTB + c * 16, asrc + (size_t)row * ROWB + c * 16);
        }
        #pragma unroll
        for (int it = 0; it < 8; it++) {       // B: 2048 chunks of 16B
            int idx = it * 256 + tid;
            int row = idx >> 4, c = idx & 15;
            cp_async16(sbase + B0_OFF + row * SSTB + c * 16, bsrc + (size_t)row * ROWB + c * 16);
        }
        CP_COMMIT();
        CP_WAIT0();
    }
    __syncthreads();

    // x2 per thread: 4 rows (mi 0..1, k2 0..1)
    float x2v[2][2];
    #pragma unroll
    for (int mi = 0; mi < 2; mi++)
        #pragma unroll
        for (int k2 = 0; k2 < 2; k2++)
            x2v[mi][k2] = g_x2[b * NPTS + n0 + wm * 32 + mi * 16 + (ln >> 2) + k2 * 8];

    // ldmatrix base addresses (k-step adds 32 B each)
    uint32_t aaddr[2], baddr[4];
    #pragma unroll
    for (int mi = 0; mi < 2; mi++)
        aaddr[mi] = sbase + A_OFF + (wm * 32 + mi * 16 + (ln & 15)) * SSTB + (ln >> 4) * 16;
    #pragma unroll
    for (int ni = 0; ni < 4; ni++)
        baddr[ni] = sbase + B0_OFF + (wn * 32 + ni * 8 + (ln & 7)) * SSTB + ((ln >> 3) & 1) * 16;

    float rm[4];   // running min of (y2 - 2dot) per row slot (mi*2+k2)
    #pragma unroll
    for (int r = 0; r < 4; r++) rm[r] = __uint_as_float(INF_BITS);

    for (int t = 0; t < 32; t++) {
        // issue next B tile into the other buffer (overlaps this tile's compute)
        if (t < 31) {
            const unsigned char* bsrc =
                (const unsigned char*)(g_By + (size_t)(b * NPTS + (t + 1) * 128) * DIM);
            uint32_t boff = sbase + (((t + 1) & 1) ? B1_OFF : B0_OFF);
            #pragma unroll
            for (int it = 0; it < 8; it++) {
                int idx = it * 256 + tid;
                int row = idx >> 4, c = idx & 15;
                cp_async16(boff + row * SSTB + c * 16, bsrc + (size_t)row * ROWB + c * 16);
            }
            CP_COMMIT();
        }

        // y2 for this tile's columns (8 per thread)
        float y2v[4][2];
        #pragma unroll
        for (int ni = 0; ni < 4; ni++)
            #pragma unroll
            for (int e = 0; e < 2; e++)
                y2v[ni][e] = g_y2[b * NPTS + t * 128 + wn * 32 + ni * 8 + (ln & 3) * 2 + e];

        const uint32_t bsel = (t & 1) ? (B1_OFF - B0_OFF) : 0u;

        float acc[2][4][4];
        #pragma unroll
        for (int mi = 0; mi < 2; mi++)
            #pragma unroll
            for (int ni = 0; ni < 4; ni++)
                #pragma unroll
                for (int k = 0; k < 4; k++) acc[mi][ni][k] = 0.0f;

        // ---- mainloop: K=128 in 8 k-steps ----
        #pragma unroll
        for (int ks = 0; ks < 8; ks++) {
            uint32_t afr[2][4], bfr[4][2];
            #pragma unroll
            for (int mi = 0; mi < 2; mi++) ldsm_x4(afr[mi], aaddr[mi] + ks * 32);
            #pragma unroll
            for (int ni = 0; ni < 4; ni++) ldsm_x2(bfr[ni], baddr[ni] + bsel + ks * 32);
            #pragma unroll
            for (int mi = 0; mi < 2; mi++)
                #pragma unroll
                for (int ni = 0; ni < 4; ni++)
                    mma_f16(acc[mi][ni], afr[mi], bfr[ni]);
        }

        // ---- epilogue: deferred mins (2 FFMA + 2 FMIN per element) ----
        float cmv[4][2];   // running min of (x2 - 2dot) per column slot
        #pragma unroll
        for (int ni = 0; ni < 4; ni++)
            #pragma unroll
            for (int e = 0; e < 2; e++) cmv[ni][e] = __uint_as_float(INF_BITS);

        #pragma unroll
        for (int mi = 0; mi < 2; mi++)
            #pragma unroll
            for (int ni = 0; ni < 4; ni++)
                #pragma unroll
                for (int k = 0; k < 4; k++) {
                    int k2 = k >> 1, e = k & 1;
                    float a = acc[mi][ni][k];
                    rm[mi * 2 + k2] = fminf(rm[mi * 2 + k2], fmaf(-2.0f, a, y2v[ni][e]));
                    cmv[ni][e]      = fminf(cmv[ni][e],      fmaf(-2.0f, a, x2v[mi][k2]));
                }

        // colmin: fold over the warp's 8 row-groups, add y2, clamp, RED.MIN
        #pragma unroll
        for (int ni = 0; ni < 4; ni++)
            #pragma unroll
            for (int e = 0; e < 2; e++) {
                float v = cmv[ni][e];
                v = fminf(v, __shfl_xor_sync(0xffffffffu, v, 4));
                v = fminf(v, __shfl_xor_sync(0xffffffffu, v, 8));
                v = fminf(v, __shfl_xor_sync(0xffffffffu, v, 16));
                if (ln < 4) {
                    float d2 = fmaxf(v + y2v[ni][e], 0.0f);
                    atomicMin(&g_colmin[b * NPTS + t * 128 + wn * 32 + ni * 8 + ln * 2 + e],
                              __float_as_uint(d2));
                }
            }

        if (t < 31) CP_WAIT0();   // next B tile landed (this thread's copies)
        __syncthreads();          // all threads' copies + all reads of old buffer done
    }

    // ---- final rowmin: fold cols across lanes, add x2, clamp, RED.MIN ----
    #pragma unroll
    for (int r = 0; r < 4; r++) {
        float v = rm[r];
        v = fminf(v, __shfl_xor_sync(0xffffffffu, v, 1));
        v = fminf(v, __shfl_xor_sync(0xffffffffu, v, 2));
        if ((ln & 3) == 0) {
            int mi = r >> 1, k2 = r & 1;
            int row = wm * 32 + mi * 16 + (ln >> 2) + k2 * 8;
            float d2 = fmaxf(v + x2v[mi][k2], 0.0f);
            atomicMin(&g_rowmin[b * NPTS + n0 + row], __float_as_uint(d2));
        }
    }
}

// ---------------------------------------------------------------------------
// Kernel 3: per-batch max over union(rowmin, colmin), sqrt, mean.
// ---------------------------------------------------------------------------
__global__ void hd_finalize(float* __restrict__ out) {
    __shared__ float s[256];
    int tid = threadIdx.x;
    float sum = 0.0f;
    for (int b = 0; b < BATCH; b++) {
        float mx = 0.0f;
        for (int i = tid; i < NPTS; i += 256) {
            mx = fmaxf(mx, __uint_as_float(g_rowmin[b * NPTS + i]));
            mx = fmaxf(mx, __uint_as_float(g_colmin[b * NPTS + i]));
        }
        s[tid] = mx;
        __syncthreads();
        for (int st = 128; st > 0; st >>= 1) {
            if (tid < st) s[tid] = fmaxf(s[tid], s[tid + st]);
            __syncthreads();
        }
        if (tid == 0) sum += sqrtf(s[0]);
        __syncthreads();
    }
    if (tid == 0) out[0] = sum * (1.0f / BATCH);
}

// ---------------------------------------------------------------------------
extern "C" void kernel_launch(void* const* d_in, const int* in_sizes, int n_in,
                              void* d_out, int out_size) {
    const float* x = (const float*)d_in[0];
    const float* y = (const float*)d_in[1];
    float* out = (float*)d_out;

    (void)cudaFuncSetAttribute(hd_main, cudaFuncAttributeMaxDynamicSharedMemorySize,
                               SMEM_BYTES);

    hd_prep<<<(2 * BATCH * NPTS * 32) / 256, 256>>>(x, y);
    hd_main<<<BATCH * 64, 256, SMEM_BYTES>>>();
    hd_finalize<<<1, 256>>>(out);
}

// round 8
// speedup vs baseline: 1.2218x; 1.2218x over previous
#include <cuda_runtime.h>
#include <cuda_fp16.h>
#include <cstdint>

// Problem constants (fixed: x,y in f32[4,4096,128])
#define BATCH 4
#define NPTS  4096
#define DIM   128
#define INF_BITS 0x7f800000u

#define ROWB   256            // bytes per row in gmem (128 fp16)
#define SSTB   272            // smem row stride bytes (68 words, 68%32==4: ldmatrix conflict-free)

// ---------------- global scratch (allocation-free rule) ----------------
__device__ __half  g_Ax[BATCH * NPTS * DIM];
__device__ __half  g_By[BATCH * NPTS * DIM];
__device__ float    g_x2[BATCH * NPTS];
__device__ float    g_y2[BATCH * NPTS];
__device__ unsigned g_rowmin[BATCH * NPTS];  // RED.MIN accumulated (clamped >=0)
__device__ unsigned g_colmin[BATCH * NPTS];  // RED.MIN accumulated (clamped >=0)

// ---------------- smem layout (bytes): M=128 tile, 2 CTAs/SM ----------------
#define A_OFF     0            // 128 * 272 = 34816
#define B0_OFF    34816
#define B1_OFF    69632
#define SMEM_BYTES 104448      // 2 CTAs x 102 KB fits the 227 KB carveout

// ---------------- PTX helpers (sm_80+ / plain sm_100-safe) ----------------
__device__ __forceinline__ uint32_t smem_u32(const void* p) {
    uint32_t a;
    asm("{ .reg .u64 t; cvta.to.shared.u64 t, %1; cvt.u32.u64 %0, t; }" : "=r"(a) : "l"(p));
    return a;
}
__device__ __forceinline__ void cp_async16(uint32_t saddr, const void* g) {
    asm volatile("cp.async.cg.shared.global [%0], [%1], 16;" :: "r"(saddr), "l"(g));
}
#define CP_COMMIT() asm volatile("cp.async.commit_group;" ::: "memory")
#define CP_WAIT0()  asm volatile("cp.async.wait_group 0;" ::: "memory")

__device__ __forceinline__ void ldsm_x4(uint32_t* r, uint32_t addr) {
    asm volatile("ldmatrix.sync.aligned.m8n8.x4.shared.b16 {%0,%1,%2,%3}, [%4];"
                 : "=r"(r[0]), "=r"(r[1]), "=r"(r[2]), "=r"(r[3]) : "r"(addr));
}
__device__ __forceinline__ void ldsm_x2(uint32_t* r, uint32_t addr) {
    asm volatile("ldmatrix.sync.aligned.m8n8.x2.shared.b16 {%0,%1}, [%2];"
                 : "=r"(r[0]), "=r"(r[1]) : "r"(addr));
}
__device__ __forceinline__ void mma_f16(float* c, const uint32_t* a, const uint32_t* b) {
    asm volatile("mma.sync.aligned.m16n8k16.row.col.f32.f16.f16.f32 "
                 "{%0,%1,%2,%3}, {%4,%5,%6,%7}, {%8,%9}, {%0,%1,%2,%3};"
                 : "+f"(c[0]), "+f"(c[1]), "+f"(c[2]), "+f"(c[3])
                 : "r"(a[0]), "r"(a[1]), "r"(a[2]), "r"(a[3]), "r"(b[0]), "r"(b[1]));
}

// ---------------------------------------------------------------------------
// Kernel 1: fp16 convert + fp32 squared norms + min-array init. Warp per row.
// ---------------------------------------------------------------------------
__global__ void hd_prep(const float* __restrict__ x, const float* __restrict__ y) {
    int gtid = blockIdx.x * blockDim.x + threadIdx.x;
    if (gtid < BATCH * NPTS) {
        g_colmin[gtid] = INF_BITS;
        g_rowmin[gtid] = INF_BITS;
    }

    int warp = gtid >> 5;
    int lane = gtid & 31;
    bool isx = warp < BATCH * NPTS;
    int row = isx ? warp : warp - BATCH * NPTS;
    const float* src = (isx ? x : y) + (size_t)row * DIM;

    float4 v = ((const float4*)src)[lane];

    __half2 p0 = __floats2half2_rn(v.x, v.y);
    __half2 p1 = __floats2half2_rn(v.z, v.w);
    uint2 pw;
    pw.x = *(unsigned*)&p0;
    pw.y = *(unsigned*)&p1;

    __half* dst = (isx ? g_Ax : g_By) + (size_t)row * DIM;
    ((uint2*)dst)[lane] = pw;

    float s = v.x * v.x + v.y * v.y + v.z * v.z + v.w * v.w;
    #pragma unroll
    for (int o = 16; o > 0; o >>= 1) s += __shfl_xor_sync(0xffffffffu, s, o);
    if (lane == 0) {
        if (isx) g_x2[row] = s;
        else     g_y2[row] = s;
    }
}

// ---------------------------------------------------------------------------
// Kernel 2: fp16 mma.sync GEMM with fused min epilogue. M-tile = 128 rows of x
// (best HMMA/LDSM ratio); the 32 m-tiles of y are SPLIT across 2 CTAs (16
// each) -> grid 256, 2 CTAs/SM, single wave on 148 SMs; co-resident CTAs hide
// each other's epilogues. Warp layout: 8 warps = 2 (M) x 4 (N), warp tile
// 64x32. Mins deferred: rowmin accumulates (y2-2dot), colmin (x2-2dot);
// norms added and clamp applied at flush (min/max commute with the clamp).
// ---------------------------------------------------------------------------
extern __shared__ unsigned char smem_raw[];

__global__ __launch_bounds__(256, 2)
void hd_main() {
    unsigned char* sm = smem_raw;
    const uint32_t sbase = smem_u32(sm);
    const int tid  = threadIdx.x;
    const int wid  = tid >> 5;
    const int ln   = tid & 31;
    const int wm   = wid >> 2;       // 0..1  (M half: 64 rows)
    const int wn   = wid & 3;        // 0..3  (N quarter: 32 cols)
    const int half = blockIdx.x & 1; // which 16-tile m-range
    const int nt   = (blockIdx.x >> 1) & 31;
    const int b    = blockIdx.x >> 6;
    const int n0   = nt * 128;
    const int t0   = half * 16;

    // ---- prologue: async-load A tile and B tile t0 (34 KB each) ----
    {
        const unsigned char* asrc = (const unsigned char*)(g_Ax + (size_t)(b * NPTS + n0) * DIM);
        const unsigned char* bsrc = (const unsigned char*)(g_By + (size_t)(b * NPTS + t0 * 128) * DIM);
        #pragma unroll
        for (int it = 0; it < 8; it++) {
            int idx = it * 256 + tid;          // 2048 chunks of 16B
            int row = idx >> 4, c = idx & 15;
            cp_async16(sbase + A_OFF  + row * SSTB + c * 16, asrc + (size_t)row * ROWB + c * 16);
            cp_async16(sbase + B0_OFF + row * SSTB + c * 16, bsrc + (size_t)row * ROWB + c * 16);
        }
        CP_COMMIT();
        CP_WAIT0();
    }
    __syncthreads();

    // x2 per thread: 8 rows (mi 0..3, k2 0..1)
    float x2v[4][2];
    #pragma unroll
    for (int mi = 0; mi < 4; mi++)
        #pragma unroll
        for (int k2 = 0; k2 < 2; k2++)
            x2v[mi][k2] = g_x2[b * NPTS + n0 + wm * 64 + mi * 16 + (ln >> 2) + k2 * 8];

    // ldmatrix base addresses (k-step adds 32 B each)
    uint32_t aaddr[4], baddr[4];
    #pragma unroll
    for (int mi = 0; mi < 4; mi++)
        aaddr[mi] = sbase + A_OFF + (wm * 64 + mi * 16 + (ln & 15)) * SSTB + (ln >> 4) * 16;
    #pragma unroll
    for (int ni = 0; ni < 4; ni++)
        baddr[ni] = sbase + B0_OFF + (wn * 32 + ni * 8 + (ln & 7)) * SSTB + ((ln >> 3) & 1) * 16;

    float rm[8];   // running min of (y2 - 2dot) per row slot (mi*2+k2)
    #pragma unroll
    for (int r = 0; r < 8; r++) rm[r] = __uint_as_float(INF_BITS);

    for (int t = t0; t < t0 + 16; t++) {
        // issue next B tile into the other buffer (overlaps this tile's compute)
        if (t < t0 + 15) {
            const unsigned char* bsrc =
                (const unsigned char*)(g_By + (size_t)(b * NPTS + (t + 1) * 128) * DIM);
            uint32_t boff = sbase + (((t + 1) & 1) ? B1_OFF : B0_OFF);
            #pragma unroll
            for (int it = 0; it < 8; it++) {
                int idx = it * 256 + tid;
                int row = idx >> 4, c = idx & 15;
                cp_async16(boff + row * SSTB + c * 16, bsrc + (size_t)row * ROWB + c * 16);
            }
            CP_COMMIT();
        }

        const uint32_t bsel = (t & 1) ? (B1_OFF - B0_OFF) : 0u;

        float acc[4][4][4];
        #pragma unroll
        for (int mi = 0; mi < 4; mi++)
            #pragma unroll
            for (int ni = 0; ni < 4; ni++)
                #pragma unroll
                for (int k = 0; k < 4; k++) acc[mi][ni][k] = 0.0f;

        // ---- mainloop: K=128 in 8 k-steps ----
        #pragma unroll
        for (int ks = 0; ks < 8; ks++) {
            uint32_t afr[4][4], bfr[4][2];
            #pragma unroll
            for (int mi = 0; mi < 4; mi++) ldsm_x4(afr[mi], aaddr[mi] + ks * 32);
            #pragma unroll
            for (int ni = 0; ni < 4; ni++) ldsm_x2(bfr[ni], baddr[ni] + bsel + ks * 32);
            #pragma unroll
            for (int mi = 0; mi < 4; mi++)
                #pragma unroll
                for (int ni = 0; ni < 4; ni++)
                    mma_f16(acc[mi][ni], afr[mi], bfr[ni]);
        }

        // y2 for this tile's columns (8 per thread), loaded late (short live range)
        float y2v[4][2];
        #pragma unroll
        for (int ni = 0; ni < 4; ni++)
            #pragma unroll
            for (int e = 0; e < 2; e++)
                y2v[ni][e] = g_y2[b * NPTS + t * 128 + wn * 32 + ni * 8 + (ln & 3) * 2 + e];

        // ---- epilogue: deferred mins (2 FFMA + 2 FMIN per element) ----
        float cmv[4][2];   // running min of (x2 - 2dot) per column slot
        #pragma unroll
        for (int ni = 0; ni < 4; ni++)
            #pragma unroll
            for (int e = 0; e < 2; e++) cmv[ni][e] = __uint_as_float(INF_BITS);

        #pragma unroll
        for (int mi = 0; mi < 4; mi++)
            #pragma unroll
            for (int ni = 0; ni < 4; ni++)
                #pragma unroll
                for (int k = 0; k < 4; k++) {
                    int k2 = k >> 1, e = k & 1;
                    float a = acc[mi][ni][k];
                    rm[mi * 2 + k2] = fminf(rm[mi * 2 + k2], fmaf(-2.0f, a, y2v[ni][e]));
                    cmv[ni][e]      = fminf(cmv[ni][e],      fmaf(-2.0f, a, x2v[mi][k2]));
                }

        // colmin: fold across the warp's 8 row-groups, add y2, clamp, RED.MIN
        #pragma unroll
        for (int ni = 0; ni < 4; ni++)
            #pragma unroll
            for (int e = 0; e < 2; e++) {
                float v = cmv[ni][e];
                v = fminf(v, __shfl_xor_sync(0xffffffffu, v, 4));
                v = fminf(v, __shfl_xor_sync(0xffffffffu, v, 8));
                v = fminf(v, __shfl_xor_sync(0xffffffffu, v, 16));
                if (ln < 4) {
                    float d2 = fmaxf(v + y2v[ni][e], 0.0f);
                    atomicMin(&g_colmin[b * NPTS + t * 128 + wn * 32 + ni * 8 + ln * 2 + e],
                              __float_as_uint(d2));
                }
            }

        if (t < t0 + 15) CP_WAIT0();  // next B tile landed (this thread's copies)
        __syncthreads();              // everyone done reading old buffer before overwrite
    }

    // ---- final rowmin: fold cols across lanes, add x2, clamp, RED.MIN ----
    #pragma unroll
    for (int r = 0; r < 8; r++) {
        float v = rm[r];
        v = fminf(v, __shfl_xor_sync(0xffffffffu, v, 1));
        v = fminf(v, __shfl_xor_sync(0xffffffffu, v, 2));
        if ((ln & 3) == 0) {
            int mi = r >> 1, k2 = r & 1;
            int row = wm * 64 + mi * 16 + (ln >> 2) + k2 * 8;
            float d2 = fmaxf(v + x2v[mi][k2], 0.0f);
            atomicMin(&g_rowmin[b * NPTS + n0 + row], __float_as_uint(d2));
        }
    }
}

// ---------------------------------------------------------------------------
// Kernel 3: per-batch max over union(rowmin, colmin), sqrt, mean.
// ---------------------------------------------------------------------------
__global__ void hd_finalize(float* __restrict__ out) {
    __shared__ float s[256];
    int tid = threadIdx.x;
    float sum = 0.0f;
    for (int b = 0; b < BATCH; b++) {
        float mx = 0.0f;
        for (int i = tid; i < NPTS; i += 256) {
            mx = fmaxf(mx, __uint_as_float(g_rowmin[b * NPTS + i]));
            mx = fmaxf(mx, __uint_as_float(g_colmin[b * NPTS + i]));
        }
        s[tid] = mx;
        __syncthreads();
        for (int st = 128; st > 0; st >>= 1) {
            if (tid < st) s[tid] = fmaxf(s[tid], s[tid + st]);
            __syncthreads();
        }
        if (tid == 0) sum += sqrtf(s[0]);
        __syncthreads();
    }
    if (tid == 0) out[0] = sum * (1.0f / BATCH);
}

// ---------------------------------------------------------------------------
extern "C" void kernel_launch(void* const* d_in, const int* in_sizes, int n_in,
                              void* d_out, int out_size) {
    const float* x = (const float*)d_in[0];
    const float* y = (const float*)d_in[1];
    float* out = (float*)d_out;

    (void)cudaFuncSetAttribute(hd_main, cudaFuncAttributeMaxDynamicSharedMemorySize,
                               SMEM_BYTES);

    hd_prep<<<(2 * BATCH * NPTS * 32) / 256, 256>>>(x, y);
    hd_main<<<BATCH * 64, 256, SMEM_BYTES>>>();
    hd_finalize<<<1, 256>>>(out);
}

// round 9
// speedup vs baseline: 1.3499x; 1.1049x over previous
#include <cuda_runtime.h>
#include <cuda_fp16.h>
#include <cstdint>

// Problem constants (fixed: x,y in f32[4,4096,128])
#define BATCH 4
#define NPTS  4096
#define DIM   128
#define INF_BITS 0x7f800000u

#define ROWB   256            // bytes per row in gmem (128 fp16)
#define SSTB   272            // smem row stride bytes (68 words, 68%32==4: ldmatrix conflict-free)

// ---------------- global scratch (allocation-free rule) ----------------
__device__ __half  g_Ax[BATCH * NPTS * DIM];
__device__ __half  g_By[BATCH * NPTS * DIM];
__device__ float    g_x2[BATCH * NPTS];
__device__ float    g_y2[BATCH * NPTS];
__device__ unsigned g_rowmin[BATCH * NPTS];  // RED.MIN accumulated (clamped >=0)
__device__ unsigned g_colmin[BATCH * NPTS];  // RED.MIN accumulated (clamped >=0)

// ---------------- smem layout (bytes): M=128 tile, 2 CTAs/SM ----------------
#define A_OFF     0            // 128 * 272 = 34816
#define B0_OFF    34816
#define B1_OFF    69632
#define SMEM_BYTES 104448      // 2 CTAs x 102 KB fits the 227 KB carveout

// ---------------- PTX helpers (sm_80+ / plain sm_100-safe) ----------------
__device__ __forceinline__ uint32_t smem_u32(const void* p) {
    uint32_t a;
    asm("{ .reg .u64 t; cvta.to.shared.u64 t, %1; cvt.u32.u64 %0, t; }" : "=r"(a) : "l"(p));
    return a;
}
__device__ __forceinline__ void cp_async16(uint32_t saddr, const void* g) {
    asm volatile("cp.async.cg.shared.global [%0], [%1], 16;" :: "r"(saddr), "l"(g));
}
#define CP_COMMIT() asm volatile("cp.async.commit_group;" ::: "memory")
#define CP_WAIT0()  asm volatile("cp.async.wait_group 0;" ::: "memory")

__device__ __forceinline__ void ldsm_x4(uint32_t* r, uint32_t addr) {
    asm volatile("ldmatrix.sync.aligned.m8n8.x4.shared.b16 {%0,%1,%2,%3}, [%4];"
                 : "=r"(r[0]), "=r"(r[1]), "=r"(r[2]), "=r"(r[3]) : "r"(addr));
}
__device__ __forceinline__ void ldsm_x2(uint32_t* r, uint32_t addr) {
    asm volatile("ldmatrix.sync.aligned.m8n8.x2.shared.b16 {%0,%1}, [%2];"
                 : "=r"(r[0]), "=r"(r[1]) : "r"(addr));
}
__device__ __forceinline__ void mma_f16(float* c, const uint32_t* a, const uint32_t* b) {
    asm volatile("mma.sync.aligned.m16n8k16.row.col.f32.f16.f16.f32 "
                 "{%0,%1,%2,%3}, {%4,%5,%6,%7}, {%8,%9}, {%0,%1,%2,%3};"
                 : "+f"(c[0]), "+f"(c[1]), "+f"(c[2]), "+f"(c[3])
                 : "r"(a[0]), "r"(a[1]), "r"(a[2]), "r"(a[3]), "r"(b[0]), "r"(b[1]));
}

// ---------------------------------------------------------------------------
// Kernel 1: fp16 convert + fp32 squared norms + min-array init.
// Half-warp (16 lanes) per row, 2 independent LDG.128 per thread (MLP=2),
// 4-level shfl reduce. Grid: 16384 warps -> 2048 CTAs of 256.
// ---------------------------------------------------------------------------
__global__ void hd_prep(const float* __restrict__ x, const float* __restrict__ y) {
    int gtid = blockIdx.x * blockDim.x + threadIdx.x;
    if (gtid < BATCH * NPTS) {
        g_colmin[gtid] = INF_BITS;
        g_rowmin[gtid] = INF_BITS;
    }

    int hw   = gtid >> 4;          // half-warp index = row index over both tensors
    int hl   = gtid & 15;          // lane within half-warp
    bool isx = hw < BATCH * NPTS;
    int row  = isx ? hw : hw - BATCH * NPTS;
    const float* src = (isx ? x : y) + (size_t)row * DIM;

    float4 v0 = ((const float4*)src)[hl];
    float4 v1 = ((const float4*)src)[hl + 16];

    __half2 a0 = __floats2half2_rn(v0.x, v0.y);
    __half2 a1 = __floats2half2_rn(v0.z, v0.w);
    __half2 b0 = __floats2half2_rn(v1.x, v1.y);
    __half2 b1 = __floats2half2_rn(v1.z, v1.w);
    uint2 pa, pb;
    pa.x = *(unsigned*)&a0; pa.y = *(unsigned*)&a1;
    pb.x = *(unsigned*)&b0; pb.y = *(unsigned*)&b1;

    __half* dst = (isx ? g_Ax : g_By) + (size_t)row * DIM;
    ((uint2*)dst)[hl]      = pa;
    ((uint2*)dst)[hl + 16] = pb;

    float s = v0.x * v0.x + v0.y * v0.y + v0.z * v0.z + v0.w * v0.w
            + v1.x * v1.x + v1.y * v1.y + v1.z * v1.z + v1.w * v1.w;
    #pragma unroll
    for (int o = 8; o > 0; o >>= 1) s += __shfl_xor_sync(0xffffffffu, s, o);
    if (hl == 0) {
        if (isx) g_x2[row] = s;
        else     g_y2[row] = s;
    }
}

// ---------------------------------------------------------------------------
// Kernel 2: fp16 mma.sync GEMM with fused min epilogue. M-tile = 128 rows of
// x; the 32 m-tiles of y SPLIT across 2 CTAs (16 each) -> grid 256, 2 CTAs/SM.
// B-prefetch for tile t+1 is interleaved one 16B chunk per k-step of tile t's
// mainloop (spreads LDGSTS issue across the HMMA stream instead of a burst).
// Colmin flush happens after the barrier, overlapping the next tile.
// Warp layout: 8 warps = 2 (M) x 4 (N), warp tile 64x32. Mins deferred:
// rowmin accumulates (y2-2dot), colmin (x2-2dot); norms + clamp at flush.
// ---------------------------------------------------------------------------
extern __shared__ unsigned char smem_raw[];

__global__ __launch_bounds__(256, 2)
void hd_main() {
    unsigned char* sm = smem_raw;
    const uint32_t sbase = smem_u32(sm);
    const int tid  = threadIdx.x;
    const int wid  = tid >> 5;
    const int ln   = tid & 31;
    const int wm   = wid >> 2;       // 0..1  (M half: 64 rows)
    const int wn   = wid & 3;        // 0..3  (N quarter: 32 cols)
    const int half = blockIdx.x & 1; // which 16-tile m-range
    const int nt   = (blockIdx.x >> 1) & 31;
    const int b    = blockIdx.x >> 6;
    const int n0   = nt * 128;
    const int t0   = half * 16;

    // per-thread chunk coords for B fills (8 chunks of 16B, one per k-step)
    const int prow = tid >> 4;          // 0..15 base row (stride 16 below is rows 0..127)
    const int pcol = tid & 15;          // 16B chunk within 256B row

    // ---- prologue: async-load A tile and B tile t0 (34 KB each) ----
    {
        const unsigned char* asrc = (const unsigned char*)(g_Ax + (size_t)(b * NPTS + n0) * DIM);
        const unsigned char* bsrc = (const unsigned char*)(g_By + (size_t)(b * NPTS + t0 * 128) * DIM);
        #pragma unroll
        for (int it = 0; it < 8; it++) {
            int row = prow + it * 16;
            cp_async16(sbase + A_OFF  + row * SSTB + pcol * 16, asrc + (size_t)row * ROWB + pcol * 16);
            cp_async16(sbase + B0_OFF + row * SSTB + pcol * 16, bsrc + (size_t)row * ROWB + pcol * 16);
        }
        CP_COMMIT();
        CP_WAIT0();
    }
    __syncthreads();

    // x2 per thread: 8 rows (mi 0..3, k2 0..1)
    float x2v[4][2];
    #pragma unroll
    for (int mi = 0; mi < 4; mi++)
        #pragma unroll
        for (int k2 = 0; k2 < 2; k2++)
            x2v[mi][k2] = g_x2[b * NPTS + n0 + wm * 64 + mi * 16 + (ln >> 2) + k2 * 8];

    // ldmatrix base addresses (k-step adds 32 B each)
    uint32_t aaddr[4], baddr[4];
    #pragma unroll
    for (int mi = 0; mi < 4; mi++)
        aaddr[mi] = sbase + A_OFF + (wm * 64 + mi * 16 + (ln & 15)) * SSTB + (ln >> 4) * 16;
    #pragma unroll
    for (int ni = 0; ni < 4; ni++)
        baddr[ni] = sbase + B0_OFF + (wn * 32 + ni * 8 + (ln & 7)) * SSTB + ((ln >> 3) & 1) * 16;

    float rm[8];   // running min of (y2 - 2dot) per row slot (mi*2+k2)
    #pragma unroll
    for (int r = 0; r < 8; r++) rm[r] = __uint_as_float(INF_BITS);

    for (int t = t0; t < t0 + 16; t++) {
        const bool pf = (t < t0 + 15);
        const unsigned char* nbsrc =
            (const unsigned char*)(g_By + (size_t)(b * NPTS + (t + 1) * 128) * DIM);
        const uint32_t nboff = sbase + (((t + 1) & 1) ? B1_OFF : B0_OFF);
        const uint32_t bsel  = (t & 1) ? (B1_OFF - B0_OFF) : 0u;

        float acc[4][4][4];
        #pragma unroll
        for (int mi = 0; mi < 4; mi++)
            #pragma unroll
            for (int ni = 0; ni < 4; ni++)
                #pragma unroll
                for (int k = 0; k < 4; k++) acc[mi][ni][k] = 0.0f;

        // ---- mainloop: K=128 in 8 k-steps; 1 prefetch chunk per thread/ks ----
        #pragma unroll
        for (int ks = 0; ks < 8; ks++) {
            if (pf) {
                int row = prow + ks * 16;
                cp_async16(nboff + row * SSTB + pcol * 16,
                           nbsrc + (size_t)row * ROWB + pcol * 16);
            }
            uint32_t afr[4][4], bfr[4][2];
            #pragma unroll
            for (int mi = 0; mi < 4; mi++) ldsm_x4(afr[mi], aaddr[mi] + ks * 32);
            #pragma unroll
            for (int ni = 0; ni < 4; ni++) ldsm_x2(bfr[ni], baddr[ni] + bsel + ks * 32);
            #pragma unroll
            for (int mi = 0; mi < 4; mi++)
                #pragma unroll
                for (int ni = 0; ni < 4; ni++)
                    mma_f16(acc[mi][ni], afr[mi], bfr[ni]);
        }
        if (pf) CP_COMMIT();

        // y2 for this tile's columns (8 per thread)
        float y2v[4][2];
        #pragma unroll
        for (int ni = 0; ni < 4; ni++)
            #pragma unroll
            for (int e = 0; e < 2; e++)
                y2v[ni][e] = g_y2[b * NPTS + t * 128 + wn * 32 + ni * 8 + (ln & 3) * 2 + e];

        // ---- epilogue: deferred mins (2 FFMA + 2 FMIN per element) ----
        float cmv[4][2];   // running min of (x2 - 2dot) per column slot
        #pragma unroll
        for (int ni = 0; ni < 4; ni++)
            #pragma unroll
            for (int e = 0; e < 2; e++) cmv[ni][e] = __uint_as_float(INF_BITS);

        #pragma unroll
        for (int mi = 0; mi < 4; mi++)
            #pragma unroll
            for (int ni = 0; ni < 4; ni++)
                #pragma unroll
                for (int k = 0; k < 4; k++) {
                    int k2 = k >> 1, e = k & 1;
                    float a = acc[mi][ni][k];
                    rm[mi * 2 + k2] = fminf(rm[mi * 2 + k2], fmaf(-2.0f, a, y2v[ni][e]));
                    cmv[ni][e]      = fminf(cmv[ni][e],      fmaf(-2.0f, a, x2v[mi][k2]));
                }

        if (pf) CP_WAIT0();   // this thread's prefetch chunks landed
        __syncthreads();      // everyone done reading old buffer before overwrite

        // colmin flush AFTER the barrier: shfl + fire-and-forget RED.MIN
        // overlap the next tile's prefetch/mainloop.
        #pragma unroll
        for (int ni = 0; ni < 4; ni++)
            #pragma unroll
            for (int e = 0; e < 2; e++) {
                float v = cmv[ni][e];
                v = fminf(v, __shfl_xor_sync(0xffffffffu, v, 4));
                v = fminf(v, __shfl_xor_sync(0xffffffffu, v, 8));
                v = fminf(v, __shfl_xor_sync(0xffffffffu, v, 16));
                if (ln < 4) {
                    float d2 = fmaxf(v + y2v[ni][e], 0.0f);
                    atomicMin(&g_colmin[b * NPTS + t * 128 + wn * 32 + ni * 8 + ln * 2 + e],
                              __float_as_uint(d2));
                }
            }
    }

    // ---- final rowmin: fold cols across lanes, add x2, clamp, RED.MIN ----
    #pragma unroll
    for (int r = 0; r < 8; r++) {
        float v = rm[r];
        v = fminf(v, __shfl_xor_sync(0xffffffffu, v, 1));
        v = fminf(v, __shfl_xor_sync(0xffffffffu, v, 2));
        if ((ln & 3) == 0) {
            int mi = r >> 1, k2 = r & 1;
            int row = wm * 64 + mi * 16 + (ln >> 2) + k2 * 8;
            float d2 = fmaxf(v + x2v[mi][k2], 0.0f);
            atomicMin(&g_rowmin[b * NPTS + n0 + row], __float_as_uint(d2));
        }
    }
}

// ---------------------------------------------------------------------------
// Kernel 3: per-batch max over union(rowmin, colmin), sqrt, mean.
// ---------------------------------------------------------------------------
__global__ void hd_finalize(float* __restrict__ out) {
    __shared__ float s[256];
    int tid = threadIdx.x;
    float sum = 0.0f;
    for (int b = 0; b < BATCH; b++) {
        float mx = 0.0f;
        for (int i = tid; i < NPTS; i += 256) {
            mx = fmaxf(mx, __uint_as_float(g_rowmin[b * NPTS + i]));
            mx = fmaxf(mx, __uint_as_float(g_colmin[b * NPTS + i]));
        }
        s[tid] = mx;
        __syncthreads();
        for (int st = 128; st > 0; st >>= 1) {
            if (tid < st) s[tid] = fmaxf(s[tid], s[tid + st]);
            __syncthreads();
        }
        if (tid == 0) sum += sqrtf(s[0]);
        __syncthreads();
    }
    if (tid == 0) out[0] = sum * (1.0f / BATCH);
}

// ---------------------------------------------------------------------------
extern "C" void kernel_launch(void* const* d_in, const int* in_sizes, int n_in,
                              void* d_out, int out_size) {
    const float* x = (const float*)d_in[0];
    const float* y = (const float*)d_in[1];
    float* out = (float*)d_out;

    (void)cudaFuncSetAttribute(hd_main, cudaFuncAttributeMaxDynamicSharedMemorySize,
                               SMEM_BYTES);

    // 2*BATCH*NPTS = 32768 rows, half-warp each -> 524288 threads -> 2048 CTAs
    hd_prep<<<2048, 256>>>(x, y);
    hd_main<<<BATCH * 64, 256, SMEM_BYTES>>>();
    hd_finalize<<<1, 256>>>(out);
}

// round 10
// speedup vs baseline: 1.4048x; 1.0407x over previous
#include <cuda_runtime.h>
#include <cuda_fp16.h>
#include <cstdint>

// Problem constants (fixed: x,y in f32[4,4096,128])
#define BATCH 4
#define NPTS  4096
#define DIM   128
#define NINF_BITS 0xff800000u   // -inf (acc-max formulation)

#define ROWB   256            // bytes per row in gmem (128 fp16)
#define SSTB   272            // smem row stride bytes (68 words, 68%32==4: ldmatrix conflict-free)

// ---------------- global scratch (allocation-free rule) ----------------
__device__ __half  g_Ax[BATCH * NPTS * DIM];
__device__ __half  g_By[BATCH * NPTS * DIM];
__device__ float    g_x2[BATCH * NPTS];     // stores -x2/2
__device__ float    g_y2[BATCH * NPTS];     // stores -y2/2
__device__ unsigned g_rowmin[BATCH * NPTS]; // RED.MIN accumulated (clamped >=0)
__device__ unsigned g_colmin[BATCH * NPTS]; // RED.MIN accumulated (clamped >=0)

// ---------------- smem layout (bytes): M=128 tile, 2 CTAs/SM ----------------
#define A_OFF     0            // 128 * 272 = 34816
#define B0_OFF    34816
#define B1_OFF    69632
#define SMEM_BYTES 104448      // 2 CTAs x 102 KB fits the 227 KB carveout

// ---------------- PTX helpers (sm_80+ / plain sm_100-safe) ----------------
__device__ __forceinline__ uint32_t smem_u32(const void* p) {
    uint32_t a;
    asm("{ .reg .u64 t; cvta.to.shared.u64 t, %1; cvt.u32.u64 %0, t; }" : "=r"(a) : "l"(p));
    return a;
}
__device__ __forceinline__ void cp_async16(uint32_t saddr, const void* g) {
    asm volatile("cp.async.cg.shared.global [%0], [%1], 16;" :: "r"(saddr), "l"(g));
}
#define CP_COMMIT() asm volatile("cp.async.commit_group;" ::: "memory")
#define CP_WAIT0()  asm volatile("cp.async.wait_group 0;" ::: "memory")

__device__ __forceinline__ void ldsm_x4(uint32_t* r, uint32_t addr) {
    asm volatile("ldmatrix.sync.aligned.m8n8.x4.shared.b16 {%0,%1,%2,%3}, [%4];"
                 : "=r"(r[0]), "=r"(r[1]), "=r"(r[2]), "=r"(r[3]) : "r"(addr));
}
__device__ __forceinline__ void mma_f16(float* c, const uint32_t* a, const uint32_t* b) {
    asm volatile("mma.sync.aligned.m16n8k16.row.col.f32.f16.f16.f32 "
                 "{%0,%1,%2,%3}, {%4,%5,%6,%7}, {%8,%9}, {%0,%1,%2,%3};"
                 : "+f"(c[0]), "+f"(c[1]), "+f"(c[2]), "+f"(c[3])
                 : "r"(a[0]), "r"(a[1]), "r"(a[2]), "r"(a[3]), "r"(b[0]), "r"(b[1]));
}

// ---------------------------------------------------------------------------
// Kernel 1: fp16 convert + (-0.5 * squared norm) + min-array init.
// Half-warp (16 lanes) per row, 2 independent LDG.128 per thread.
// ---------------------------------------------------------------------------
__global__ void hd_prep(const float* __restrict__ x, const float* __restrict__ y) {
    int gtid = blockIdx.x * blockDim.x + threadIdx.x;
    if (gtid < BATCH * NPTS) {
        g_colmin[gtid] = 0x7f800000u;   // +inf
        g_rowmin[gtid] = 0x7f800000u;
    }

    int hw   = gtid >> 4;
    int hl   = gtid & 15;
    bool isx = hw < BATCH * NPTS;
    int row  = isx ? hw : hw - BATCH * NPTS;
    const float* src = (isx ? x : y) + (size_t)row * DIM;

    float4 v0 = ((const float4*)src)[hl];
    float4 v1 = ((const float4*)src)[hl + 16];

    __half2 a0 = __floats2half2_rn(v0.x, v0.y);
    __half2 a1 = __floats2half2_rn(v0.z, v0.w);
    __half2 b0 = __floats2half2_rn(v1.x, v1.y);
    __half2 b1 = __floats2half2_rn(v1.z, v1.w);
    uint2 pa, pb;
    pa.x = *(unsigned*)&a0; pa.y = *(unsigned*)&a1;
    pb.x = *(unsigned*)&b0; pb.y = *(unsigned*)&b1;

    __half* dst = (isx ? g_Ax : g_By) + (size_t)row * DIM;
    ((uint2*)dst)[hl]      = pa;
    ((uint2*)dst)[hl + 16] = pb;

    float s = v0.x * v0.x + v0.y * v0.y + v0.z * v0.z + v0.w * v0.w
            + v1.x * v1.x + v1.y * v1.y + v1.z * v1.z + v1.w * v1.w;
    #pragma unroll
    for (int o = 8; o > 0; o >>= 1) s += __shfl_xor_sync(0xffffffffu, s, o);
    if (hl == 0) {
        float h = -0.5f * s;
        if (isx) g_x2[row] = h;
        else     g_y2[row] = h;
    }
}

// ---------------------------------------------------------------------------
// Kernel 2: fp16 mma.sync GEMM with ACC-PRELOADED min epilogue.
// acc is initialized to -(x2+y2)/2, so after accumulating the dot product
// acc = -d2/2 and min(d2) == max(acc): the per-element epilogue is 2 FMAX.
// The -2 scale + clamp apply once at flush (monotone decreasing map).
// M-tile = 128 rows of x; 32 m-tiles of y split across 2 CTAs (16 each) ->
// grid 256, 2 CTAs/SM. B prefetch interleaved into the k-loop; y2 (-y2/2)
// prefetched one tile ahead (acc init depends on it). B frags via ldsm_x4.
// ---------------------------------------------------------------------------
extern __shared__ unsigned char smem_raw[];

__global__ __launch_bounds__(256, 2)
void hd_main() {
    unsigned char* sm = smem_raw;
    const uint32_t sbase = smem_u32(sm);
    const int tid  = threadIdx.x;
    const int wid  = tid >> 5;
    const int ln   = tid & 31;
    const int wm   = wid >> 2;       // 0..1  (M half: 64 rows)
    const int wn   = wid & 3;        // 0..3  (N quarter: 32 cols)
    const int half = blockIdx.x & 1;
    const int nt   = (blockIdx.x >> 1) & 31;
    const int b    = blockIdx.x >> 6;
    const int n0   = nt * 128;
    const int t0   = half * 16;

    const int prow = tid >> 4;          // base row for fills
    const int pcol = tid & 15;          // 16B chunk within row

    // ---- prologue: async-load A tile and B tile t0 ----
    {
        const unsigned char* asrc = (const unsigned char*)(g_Ax + (size_t)(b * NPTS + n0) * DIM);
        const unsigned char* bsrc = (const unsigned char*)(g_By + (size_t)(b * NPTS + t0 * 128) * DIM);
        #pragma unroll
        for (int it = 0; it < 8; it++) {
            int row = prow + it * 16;
            cp_async16(sbase + A_OFF  + row * SSTB + pcol * 16, asrc + (size_t)row * ROWB + pcol * 16);
            cp_async16(sbase + B0_OFF + row * SSTB + pcol * 16, bsrc + (size_t)row * ROWB + pcol * 16);
        }
        CP_COMMIT();
        CP_WAIT0();
    }
    __syncthreads();

    // hx = -x2/2 per thread: 8 rows (mi 0..3, k2 0..1)
    float hx[4][2];
    #pragma unroll
    for (int mi = 0; mi < 4; mi++)
        #pragma unroll
        for (int k2 = 0; k2 < 2; k2++)
            hx[mi][k2] = g_x2[b * NPTS + n0 + wm * 64 + mi * 16 + (ln >> 2) + k2 * 8];

    // hy = -y2/2 for tile t0 (prefetched one tile ahead inside the loop)
    float hy[4][2];
    #pragma unroll
    for (int ni = 0; ni < 4; ni++)
        #pragma unroll
        for (int e = 0; e < 2; e++)
            hy[ni][e] = g_y2[b * NPTS + t0 * 128 + wn * 32 + ni * 8 + (ln & 3) * 2 + e];

    // ldmatrix base addresses (k-step adds 32 B each)
    uint32_t aaddr[4], baddr[2];
    #pragma unroll
    for (int mi = 0; mi < 4; mi++)
        aaddr[mi] = sbase + A_OFF + (wm * 64 + mi * 16 + (ln & 15)) * SSTB + (ln >> 4) * 16;
    // B via ldsm_x4: matrices [ni-even k-lo][ni-even k-hi][ni-odd k-lo][ni-odd k-hi]
    #pragma unroll
    for (int pr = 0; pr < 2; pr++)
        baddr[pr] = sbase + B0_OFF +
                    (wn * 32 + pr * 16 + ((ln >> 4) & 1) * 8 + (ln & 7)) * SSTB +
                    ((ln >> 3) & 1) * 16;

    float rm[8];   // running MAX of acc per row slot (mi*2+k2)
    #pragma unroll
    for (int r = 0; r < 8; r++) rm[r] = __uint_as_float(NINF_BITS);

    for (int t = t0; t < t0 + 16; t++) {
        const bool pf = (t < t0 + 15);
        const unsigned char* nbsrc =
            (const unsigned char*)(g_By + (size_t)(b * NPTS + (t + 1) * 128) * DIM);
        const uint32_t nboff = sbase + (((t + 1) & 1) ? B1_OFF : B0_OFF);
        const uint32_t bsel  = (t & 1) ? (B1_OFF - B0_OFF) : 0u;

        // acc preload: -(x2+y2)/2 (replaces zero-init; 1 FADD per element)
        float acc[4][4][4];
        #pragma unroll
        for (int mi = 0; mi < 4; mi++)
            #pragma unroll
            for (int ni = 0; ni < 4; ni++)
                #pragma unroll
                for (int k = 0; k < 4; k++)
                    acc[mi][ni][k] = hx[mi][k >> 1] + hy[ni][k & 1];

        // prefetch hy for tile t+1 (lands during this tile's mainloop)
        {
            int tn = pf ? (t + 1) : t0;   // harmless in-range addr on last tile
            #pragma unroll
            for (int ni = 0; ni < 4; ni++)
                #pragma unroll
                for (int e = 0; e < 2; e++)
                    hy[ni][e] = g_y2[b * NPTS + tn * 128 + wn * 32 + ni * 8 + (ln & 3) * 2 + e];
        }

        // ---- mainloop: K=128 in 8 k-steps; 1 B-prefetch chunk per thread/ks ----
        #pragma unroll
        for (int ks = 0; ks < 8; ks++) {
            if (pf) {
                int row = prow + ks * 16;
                cp_async16(nboff + row * SSTB + pcol * 16,
                           nbsrc + (size_t)row * ROWB + pcol * 16);
            }
            uint32_t afr[4][4], bq[2][4];
            #pragma unroll
            for (int mi = 0; mi < 4; mi++) ldsm_x4(afr[mi], aaddr[mi] + ks * 32);
            #pragma unroll
            for (int pr = 0; pr < 2; pr++) ldsm_x4(bq[pr], baddr[pr] + bsel + ks * 32);
            #pragma unroll
            for (int mi = 0; mi < 4; mi++)
                #pragma unroll
                for (int ni = 0; ni < 4; ni++)
                    mma_f16(acc[mi][ni], afr[mi], &bq[ni >> 1][(ni & 1) * 2]);
        }
        if (pf) CP_COMMIT();

        // ---- epilogue: 2 FMAX per element ----
        float cmv[4][2];   // running MAX of acc per column slot
        #pragma unroll
        for (int ni = 0; ni < 4; ni++)
            #pragma unroll
            for (int e = 0; e < 2; e++) cmv[ni][e] = __uint_as_float(NINF_BITS);

        #pragma unroll
        for (int mi = 0; mi < 4; mi++)
            #pragma unroll
            for (int ni = 0; ni < 4; ni++)
                #pragma unroll
                for (int k = 0; k < 4; k++) {
                    float a = acc[mi][ni][k];
                    rm[mi * 2 + (k >> 1)] = fmaxf(rm[mi * 2 + (k >> 1)], a);
                    cmv[ni][k & 1]        = fmaxf(cmv[ni][k & 1], a);
                }

        if (pf) CP_WAIT0();   // this thread's prefetch chunks landed
        __syncthreads();      // everyone done reading old buffer before overwrite

        // colmin flush AFTER the barrier: shfl-max + fire-and-forget RED.MIN
        #pragma unroll
        for (int ni = 0; ni < 4; ni++)
            #pragma unroll
            for (int e = 0; e < 2; e++) {
                float v = cmv[ni][e];
                v = fmaxf(v, __shfl_xor_sync(0xffffffffu, v, 4));
                v = fmaxf(v, __shfl_xor_sync(0xffffffffu, v, 8));
                v = fmaxf(v, __shfl_xor_sync(0xffffffffu, v, 16));
                if (ln < 4) {
                    float d2 = fmaxf(-2.0f * v, 0.0f);
                    atomicMin(&g_colmin[b * NPTS + t * 128 + wn * 32 + ni * 8 + ln * 2 + e],
                              __float_as_uint(d2));
                }
            }
    }

    // ---- final rowmin: fold cols across lanes, scale, clamp, RED.MIN ----
    #pragma unroll
    for (int r = 0; r < 8; r++) {
        float v = rm[r];
        v = fmaxf(v, __shfl_xor_sync(0xffffffffu, v, 1));
        v = fmaxf(v, __shfl_xor_sync(0xffffffffu, v, 2));
        if ((ln & 3) == 0) {
            int row = wm * 64 + (r >> 1) * 16 + (ln >> 2) + (r & 1) * 8;
            float d2 = fmaxf(-2.0f * v, 0.0f);
            atomicMin(&g_rowmin[b * NPTS + n0 + row], __float_as_uint(d2));
        }
    }
}

// ---------------------------------------------------------------------------
// Kernel 3: per-batch max over union(rowmin, colmin), sqrt, mean.
// ---------------------------------------------------------------------------
__global__ void hd_finalize(float* __restrict__ out) {
    __shared__ float s[256];
    int tid = threadIdx.x;
    float sum = 0.0f;
    for (int b = 0; b < BATCH; b++) {
        float mx = 0.0f;
        for (int i = tid; i < NPTS; i += 256) {
            mx = fmaxf(mx, __uint_as_float(g_rowmin[b * NPTS + i]));
            mx = fmaxf(mx, __uint_as_float(g_colmin[b * NPTS + i]));
        }
        s[tid] = mx;
        __syncthreads();
        for (int st = 128; st > 0; st >>= 1) {
            if (tid < st) s[tid] = fmaxf(s[tid], s[tid + st]);
            __syncthreads();
        }
        if (tid == 0) sum += sqrtf(s[0]);
        __syncthreads();
    }
    if (tid == 0) out[0] = sum * (1.0f / BATCH);
}

// ---------------------------------------------------------------------------
extern "C" void kernel_launch(void* const* d_in, const int* in_sizes, int n_in,
                              void* d_out, int out_size) {
    const float* x = (const float*)d_in[0];
    const float* y = (const float*)d_in[1];
    float* out = (float*)d_out;

    (void)cudaFuncSetAttribute(hd_main, cudaFuncAttributeMaxDynamicSharedMemorySize,
                               SMEM_BYTES);

    hd_prep<<<2048, 256>>>(x, y);
    hd_main<<<BATCH * 64, 256, SMEM_BYTES>>>();
    hd_finalize<<<1, 256>>>(out);
}